// round 14
// baseline (speedup 1.0000x reference)
#include <cuda_runtime.h>
#include <cuda_fp16.h>
#include <math.h>
#include <stdint.h>

#define NN 50000
#define EE 1600000
#define NBLK 49   // ceil(NN/1024)

typedef unsigned long long u64;

// ---------------- scratch ----------------
__device__ int   g_cnt[NN];
__device__ int   g_rowptr[NN + 1];
__device__ int   g_wp[NN];
__device__ int   g_col[EE];
__device__ float g_dinv[NN];
__device__ int   g_bsum[64];
__device__ int   g_bar;
__device__ __half g_hb  [(size_t)NN * 64];    // fp16: dinv .* (x@Wb)
__device__ __half g_xb  [(size_t)NN * 64];    // fp16: dinv .* relu(agg+bb)
__device__ __half g_a2  [(size_t)NN * 64];    // fp16: agg(xb')
__device__ __half g_xsw1[(size_t)NN * 128];   // fp16: dinv .* [xs1|xw1]
__device__ __half g_a3  [(size_t)NN * 128];   // fp16: agg(xsw1')

// precomputed bf16 hi/lo weight splits, layout H[kp * N + n] = pack(W[2kp][n], W[2kp+1][n])
__device__ uint32_t g_WbH [320 * 64], g_WbL [320 * 64];
__device__ uint32_t g_Ws1H[32 * 64],  g_Ws1L[32 * 64];
__device__ uint32_t g_Ww1H[32 * 64],  g_Ww1L[32 * 64];
__device__ uint32_t g_Ws2H[32 * 640], g_Ws2L[32 * 640];
__device__ uint32_t g_Ww2H[32 * 640], g_Ww2L[32 * 640];

// ---------------- bf16 split helpers ----------------
__device__ __forceinline__ uint32_t cvt_bf2(float a, float b) {
    uint32_t r;
    asm("cvt.rn.satfinite.bf16x2.f32 %0, %1, %2;" : "=r"(r) : "f"(b), "f"(a));
    return r;
}
__device__ __forceinline__ float bf_lo_f(uint32_t h) { return __uint_as_float((h & 0xFFFFu) << 16); }
__device__ __forceinline__ float bf_hi_f(uint32_t h) { return __uint_as_float(h & 0xFFFF0000u); }

#define MMA_BF16(d0, d1, d2, d3, a0, a1, a2, a3, b0, b1) \
    asm volatile("mma.sync.aligned.m16n8k16.row.col.f32.bf16.bf16.f32 " \
        "{%0,%1,%2,%3}, {%4,%5,%6,%7}, {%8,%9}, {%0,%1,%2,%3};" \
        : "+f"(d0), "+f"(d1), "+f"(d2), "+f"(d3) \
        : "r"(a0), "r"(a1), "r"(a2), "r"(a3), "r"(b0), "r"(b1))

// ---------------- weight prep ----------------
__device__ __forceinline__ void conv_pair(const float* __restrict__ W, int N, int i,
                                          uint32_t* __restrict__ H, uint32_t* __restrict__ L) {
    int kp = i / N, n = i - kp * N;
    float f0 = W[(size_t)(2 * kp)     * N + n];
    float f1 = W[(size_t)(2 * kp + 1) * N + n];
    uint32_t h = cvt_bf2(f0, f1);
    float r0 = f0 - bf_lo_f(h), r1 = f1 - bf_hi_f(h);
    H[i] = h;
    L[i] = cvt_bf2(r0, r1);
}

// fused: blocks [0,256) prep weights; blocks [256, ...) count degrees. Also resets g_bar.
__global__ void count_prep_kernel(const int4* __restrict__ edges2,
                                  const float* __restrict__ Wb,
                                  const float* __restrict__ Ws1,
                                  const float* __restrict__ Ww1,
                                  const float* __restrict__ Ws2,
                                  const float* __restrict__ Ww2) {
    if (blockIdx.x == 0 && threadIdx.x == 0) g_bar = 0;
    if (blockIdx.x < 256) {
        int idx = blockIdx.x * 256 + threadIdx.x;
        if (idx < 20480)      conv_pair(Wb,  64,  idx,          g_WbH,  g_WbL);
        else if (idx < 22528) conv_pair(Ws1, 64,  idx - 20480,  g_Ws1H, g_Ws1L);
        else if (idx < 24576) conv_pair(Ww1, 64,  idx - 22528,  g_Ww1H, g_Ww1L);
        else if (idx < 45056) conv_pair(Ws2, 640, idx - 24576,  g_Ws2H, g_Ws2L);
        else                  conv_pair(Ww2, 640, idx - 45056,  g_Ww2H, g_Ww2L);
    } else {
        int e = (blockIdx.x - 256) * 256 + threadIdx.x;
        if (e < EE / 2) {
            int4 ed = edges2[e];
            atomicAdd(&g_cnt[ed.y], 1);
            atomicAdd(&g_cnt[ed.w], 1);
        }
    }
}

// fused degsum + scan + apply, one launch, spin grid-barrier (49 blocks, all resident)
__global__ void degscan_kernel() {
    __shared__ int warpsums[32];
    __shared__ int sb[64];
    int tid = threadIdx.x, lane = tid & 31, wid = tid >> 5;
    int i = blockIdx.x * 1024 + tid;
    int v = (i < NN) ? g_cnt[i] : 0;
    if (i < NN) g_dinv[i] = rsqrtf((float)v + 1.0f);

    // block sum
    int x = v;
    #pragma unroll
    for (int off = 16; off; off >>= 1) x += __shfl_down_sync(0xffffffffu, x, off);
    if (lane == 0) warpsums[wid] = x;
    __syncthreads();
    if (wid == 0) {
        int y = (lane < 32) ? warpsums[lane] : 0;
        #pragma unroll
        for (int off = 16; off; off >>= 1) y += __shfl_down_sync(0xffffffffu, y, off);
        if (lane == 0) g_bsum[blockIdx.x] = y;
    }
    __syncthreads();

    // grid barrier
    if (tid == 0) {
        __threadfence();
        atomicAdd(&g_bar, 1);
        while (*(volatile int*)&g_bar < NBLK) { }
    }
    __syncthreads();
    __threadfence();

    // redundant scan of 49 block sums
    if (tid < 64) sb[tid] = (tid < NBLK) ? g_bsum[tid] : 0;
    __syncthreads();
    #pragma unroll
    for (int off = 1; off < 64; off <<= 1) {
        int t = 0;
        if (tid < 64 && tid >= off) t = sb[tid - off];
        __syncthreads();
        if (tid < 64) sb[tid] += t;
        __syncthreads();
    }
    if (blockIdx.x == 0 && tid == 0) g_rowptr[NN] = sb[NBLK - 1];
    int boff = (blockIdx.x > 0) ? sb[blockIdx.x - 1] : 0;

    // per-element exclusive scan
    int xs = v;
    #pragma unroll
    for (int off = 1; off < 32; off <<= 1) {
        int y = __shfl_up_sync(0xffffffffu, xs, off);
        if (lane >= off) xs += y;
    }
    if (lane == 31) warpsums[wid] = xs;
    __syncthreads();
    if (wid == 0) {
        int w = warpsums[lane];
        #pragma unroll
        for (int off = 1; off < 32; off <<= 1) {
            int y = __shfl_up_sync(0xffffffffu, w, off);
            if (lane >= off) w += y;
        }
        warpsums[lane] = w;
    }
    __syncthreads();
    int excl = boff + ((wid > 0) ? warpsums[wid - 1] : 0) + xs - v;
    if (i < NN) {
        g_rowptr[i] = excl;
        g_wp[i]     = excl;
    }
}

__global__ void fill_kernel(const int4* __restrict__ edges2) {
    int e = blockIdx.x * blockDim.x + threadIdx.x;
    if (e < EE / 2) {
        int4 ed = edges2[e];
        int p0 = atomicAdd(&g_wp[ed.y], 1);
        g_col[p0] = ed.x;
        int p1 = atomicAdd(&g_wp[ed.w], 1);
        g_col[p1] = ed.z;
    }
}

// ---------------- aggregation (R12 structure, fp16 in, fp16/fp32 out) ----------------
template<int OUTH, int PRE, int RELU>
__global__ void agg64p_kernel(const __half2* __restrict__ X, void* __restrict__ out,
                              const float* __restrict__ bias) {
    int idx  = blockIdx.x * blockDim.x + threadIdx.x;
    int node = idx >> 5;
    if (node >= NN) return;
    int lane = idx & 31;
    float2 v = __half22float2(X[node * 32 + lane]);
    float ax = v.x, ay = v.y;
    float bx = 0.f, by = 0.f;
    int e = g_rowptr[node], end = g_rowptr[node + 1];
    while (e < end) {
        int n = end - e;
        if (n > 32) n = 32;
        int c = (lane < n) ? __ldg(&g_col[e + lane]) : 0;
        int j = 0;
        for (; j + 4 <= n; j += 4) {
            int s0 = __shfl_sync(0xffffffffu, c, j);
            int s1 = __shfl_sync(0xffffffffu, c, j + 1);
            int s2 = __shfl_sync(0xffffffffu, c, j + 2);
            int s3 = __shfl_sync(0xffffffffu, c, j + 3);
            float2 u0 = __half22float2(X[s0 * 32 + lane]);
            float2 u1 = __half22float2(X[s1 * 32 + lane]);
            float2 u2 = __half22float2(X[s2 * 32 + lane]);
            float2 u3 = __half22float2(X[s3 * 32 + lane]);
            ax += u0.x + u1.x; ay += u0.y + u1.y;
            bx += u2.x + u3.x; by += u2.y + u3.y;
        }
        for (; j < n; j++) {
            int s = __shfl_sync(0xffffffffu, c, j);
            float2 u = __half22float2(X[s * 32 + lane]);
            ax += u.x; ay += u.y;
        }
        e += n;
    }
    ax += bx; ay += by;
    float dv = g_dinv[node];
    ax *= dv; ay *= dv;
    if (bias) { ax += bias[lane * 2]; ay += bias[lane * 2 + 1]; }
    if (RELU) { ax = fmaxf(ax, 0.f); ay = fmaxf(ay, 0.f); }
    if (PRE) { ax *= dv; ay *= dv; }
    if (OUTH) ((__half2*)out)[node * 32 + lane] = __floats2half2_rn(ax, ay);
    else      ((float2*)out)[node * 32 + lane]  = make_float2(ax, ay);
}

__global__ void agg128p_kernel(const uint2* __restrict__ X, __half* __restrict__ out) {
    int idx  = blockIdx.x * blockDim.x + threadIdx.x;
    int node = idx >> 5;
    if (node >= NN) return;
    int lane = idx & 31;
    uint2 raw = X[node * 32 + lane];
    float2 p0 = __half22float2(*(const __half2*)&raw.x);
    float2 p1 = __half22float2(*(const __half2*)&raw.y);
    float a0 = p0.x, a1 = p0.y, a2 = p1.x, a3 = p1.y;
    float b0 = 0.f, b1 = 0.f, b2 = 0.f, b3 = 0.f;
    int e = g_rowptr[node], end = g_rowptr[node + 1];
    while (e < end) {
        int n = end - e;
        if (n > 32) n = 32;
        int c = (lane < n) ? __ldg(&g_col[e + lane]) : 0;
        int j = 0;
        for (; j + 4 <= n; j += 4) {
            int s0 = __shfl_sync(0xffffffffu, c, j);
            int s1 = __shfl_sync(0xffffffffu, c, j + 1);
            int s2 = __shfl_sync(0xffffffffu, c, j + 2);
            int s3 = __shfl_sync(0xffffffffu, c, j + 3);
            uint2 r0 = X[s0 * 32 + lane];
            uint2 r1 = X[s1 * 32 + lane];
            uint2 r2 = X[s2 * 32 + lane];
            uint2 r3 = X[s3 * 32 + lane];
            float2 q;
            q = __half22float2(*(const __half2*)&r0.x); a0 += q.x; a1 += q.y;
            q = __half22float2(*(const __half2*)&r0.y); a2 += q.x; a3 += q.y;
            q = __half22float2(*(const __half2*)&r1.x); b0 += q.x; b1 += q.y;
            q = __half22float2(*(const __half2*)&r1.y); b2 += q.x; b3 += q.y;
            q = __half22float2(*(const __half2*)&r2.x); a0 += q.x; a1 += q.y;
            q = __half22float2(*(const __half2*)&r2.y); a2 += q.x; a3 += q.y;
            q = __half22float2(*(const __half2*)&r3.x); b0 += q.x; b1 += q.y;
            q = __half22float2(*(const __half2*)&r3.y); b2 += q.x; b3 += q.y;
        }
        for (; j < n; j++) {
            int s = __shfl_sync(0xffffffffu, c, j);
            uint2 r = X[s * 32 + lane];
            float2 q;
            q = __half22float2(*(const __half2*)&r.x); a0 += q.x; a1 += q.y;
            q = __half22float2(*(const __half2*)&r.y); a2 += q.x; a3 += q.y;
        }
        e += n;
    }
    a0 += b0; a1 += b1; a2 += b2; a3 += b3;
    float dv = g_dinv[node];
    __half2 o0 = __floats2half2_rn(a0 * dv, a1 * dv);
    __half2 o1 = __floats2half2_rn(a2 * dv, a3 * dv);
    uint2 w;
    w.x = *(uint32_t*)&o0;
    w.y = *(uint32_t*)&o1;
    ((uint2*)out)[node * 32 + lane] = w;
}

// ---------------- unified HMMA split-bf16 GEMM (precomputed B splits; A fp32 or fp16) ----------------
template<int NT, int RELU, int BIAS, int OUTH, int RS, int AHALF>
__global__ void __launch_bounds__(256)
hmma_gemm_kernel(const void* __restrict__ Avoid, int lda, int K,
                 const uint32_t* __restrict__ BH0, const uint32_t* __restrict__ BL0,
                 const uint32_t* __restrict__ BH1, const uint32_t* __restrict__ BL1,
                 const float* __restrict__ bias0, const float* __restrict__ bias1,
                 const float* __restrict__ rowscale,
                 void* __restrict__ C, int ldc) {
    extern __shared__ char smem[];
    uint32_t* Ah = (uint32_t*)smem;
    uint32_t* Al = (uint32_t*)(smem + 18432);
    uint32_t* Bh = (uint32_t*)(smem + 36864);
    uint32_t* Bl = (uint32_t*)(smem + 36864 + NT * 144);

    int tid  = threadIdx.x;
    int wid  = tid >> 5, lane = tid & 31;
    int gr   = lane >> 2;
    int qc   = lane & 3;
    int row0 = blockIdx.x * 128;
    constexpr int NF = NT / 8;

    float d[NF][4];
    #pragma unroll
    for (int nf = 0; nf < NF; nf++) {
        d[nf][0] = 0.f; d[nf][1] = 0.f; d[nf][2] = 0.f; d[nf][3] = 0.f;
    }

    for (int k0 = 0; k0 < K; k0 += 64) {
        #pragma unroll
        for (int j = 0; j < 16; j++) {
            int idx = tid + j * 256;
            int r = idx >> 5, cp = idx & 31;
            float2 v = make_float2(0.f, 0.f);
            int grow = row0 + r;
            if (grow < NN) {
                if (AHALF)
                    v = __half22float2(*(const __half2*)((const __half*)Avoid + (size_t)grow * lda + k0 + 2 * cp));
                else
                    v = *(const float2*)((const float*)Avoid + (size_t)grow * lda + k0 + 2 * cp);
            }
            uint32_t h = cvt_bf2(v.x, v.y);
            float rx = v.x - bf_lo_f(h), ry = v.y - bf_hi_f(h);
            Ah[r * 36 + cp] = h;
            Al[r * 36 + cp] = cvt_bf2(rx, ry);
        }
        #pragma unroll
        for (int j = 0; j < NT / 8; j++) {
            int idx = tid + j * 256;
            int n  = idx % NT;
            int kp = idx / NT;
            int gkp = (k0 >> 1) + kp;
            const uint32_t* H = BH0;
            const uint32_t* L = BL0;
            int cc = n;
            if (NT == 128 && n >= 64) { H = BH1; L = BL1; cc = n - 64; }
            Bh[n * 36 + kp] = H[gkp * 64 + cc];
            Bl[n * 36 + kp] = L[gkp * 64 + cc];
        }
        __syncthreads();

        uint32_t ah[4][4], al[4][4];
        int ar0 = wid * 16 + gr;
        #pragma unroll
        for (int ks = 0; ks < 4; ks++) {
            int cp0 = ks * 8 + qc;
            ah[ks][0] = Ah[ar0 * 36 + cp0];
            ah[ks][1] = Ah[(ar0 + 8) * 36 + cp0];
            ah[ks][2] = Ah[ar0 * 36 + cp0 + 4];
            ah[ks][3] = Ah[(ar0 + 8) * 36 + cp0 + 4];
            al[ks][0] = Al[ar0 * 36 + cp0];
            al[ks][1] = Al[(ar0 + 8) * 36 + cp0];
            al[ks][2] = Al[ar0 * 36 + cp0 + 4];
            al[ks][3] = Al[(ar0 + 8) * 36 + cp0 + 4];
        }

        #pragma unroll
        for (int nf = 0; nf < NF; nf++) {
            int bn = nf * 8 + gr;
            #pragma unroll
            for (int ks = 0; ks < 4; ks++) {
                int kp0 = ks * 8 + qc;
                uint32_t b0 = Bh[bn * 36 + kp0];
                uint32_t b1 = Bh[bn * 36 + kp0 + 4];
                uint32_t c0 = Bl[bn * 36 + kp0];
                uint32_t c1 = Bl[bn * 36 + kp0 + 4];
                MMA_BF16(d[nf][0], d[nf][1], d[nf][2], d[nf][3],
                         ah[ks][0], ah[ks][1], ah[ks][2], ah[ks][3], b0, b1);
                MMA_BF16(d[nf][0], d[nf][1], d[nf][2], d[nf][3],
                         al[ks][0], al[ks][1], al[ks][2], al[ks][3], b0, b1);
                MMA_BF16(d[nf][0], d[nf][1], d[nf][2], d[nf][3],
                         ah[ks][0], ah[ks][1], ah[ks][2], ah[ks][3], c0, c1);
            }
        }
        __syncthreads();
    }

    int r1 = row0 + wid * 16 + gr;
    int r2 = r1 + 8;
    float rs1 = 1.f, rs2 = 1.f;
    if (RS) {
        if (r1 < NN) rs1 = rowscale[r1];
        if (r2 < NN) rs2 = rowscale[r2];
    }
    #pragma unroll
    for (int nf = 0; nf < NF; nf++) {
        int col = nf * 8 + 2 * qc;
        float bb0 = 0.f, bb1 = 0.f;
        if (BIAS) {
            const float* bp = bias0;
            int cc = col;
            if (NT == 128 && col >= 64 && bias1) { bp = bias1; cc = col - 64; }
            bb0 = bp[cc]; bb1 = bp[cc + 1];
        }
        float o0 = d[nf][0] + bb0, o1 = d[nf][1] + bb1;
        float o2 = d[nf][2] + bb0, o3 = d[nf][3] + bb1;
        if (RELU) {
            o0 = fmaxf(o0, 0.f); o1 = fmaxf(o1, 0.f);
            o2 = fmaxf(o2, 0.f); o3 = fmaxf(o3, 0.f);
        }
        if (RS) { o0 *= rs1; o1 *= rs1; o2 *= rs2; o3 *= rs2; }
        if (OUTH) {
            if (r1 < NN) *(__half2*)((__half*)C + (size_t)r1 * ldc + col) = __floats2half2_rn(o0, o1);
            if (r2 < NN) *(__half2*)((__half*)C + (size_t)r2 * ldc + col) = __floats2half2_rn(o2, o3);
        } else {
            if (r1 < NN) *(float2*)((float*)C + (size_t)r1 * ldc + col) = make_float2(o0, o1);
            if (r2 < NN) *(float2*)((float*)C + (size_t)r2 * ldc + col) = make_float2(o2, o3);
        }
    }
}

// ---------------- s2/w2: HMMA split-bf16, precomputed W splits, a3 fp16 ----------------
#define OH_SMEM 60416

__global__ void __launch_bounds__(256)
out_hmma_kernel(const __half* __restrict__ a3,
                const float* __restrict__ bs2, const float* __restrict__ bw2,
                float* __restrict__ out) {
    extern __shared__ char smem[];
    float*    sbias = (float*)smem;
    uint32_t* Ah = (uint32_t*)(smem + 5120);
    uint32_t* Al = (uint32_t*)(smem + 23552);
    uint32_t* Bh = (uint32_t*)(smem + 41984);
    uint32_t* Bl = (uint32_t*)(smem + 51200);

    int tid  = threadIdx.x;
    int wid  = tid >> 5, lane = tid & 31;
    int gr   = lane >> 2;
    int qc   = lane & 3;
    int row0 = blockIdx.x * 128;

    for (int i = tid; i < 640; i += 256) { sbias[i] = bs2[i]; sbias[640 + i] = bw2[i]; }

    #pragma unroll 1
    for (int br = 0; br < 2; br++) {
        __syncthreads();
        for (int idx = tid; idx < 128 * 32; idx += 256) {
            int r  = idx >> 5;
            int cp = idx & 31;
            float2 v = make_float2(0.f, 0.f);
            int grow = row0 + r;
            if (grow < NN)
                v = __half22float2(*(const __half2*)(a3 + (size_t)grow * 128 + br * 64 + 2 * cp));
            uint32_t h = cvt_bf2(v.x, v.y);
            float rx = v.x - bf_lo_f(h), ry = v.y - bf_hi_f(h);
            Ah[r * 36 + cp] = h;
            Al[r * 36 + cp] = cvt_bf2(rx, ry);
        }
        __syncthreads();
        const uint32_t* WH = br ? g_Ww2H : g_Ws2H;
        const uint32_t* WL = br ? g_Ww2L : g_Ws2L;
        const float* bp = sbias + br * 640;

        #pragma unroll 1
        for (int tile = 0; tile < 10; tile++) {
            for (int idx = tid; idx < 64 * 32; idx += 256) {
                int n  = idx & 63;
                int kp = idx >> 6;
                Bh[n * 36 + kp] = WH[kp * 640 + tile * 64 + n];
                Bl[n * 36 + kp] = WL[kp * 640 + tile * 64 + n];
            }
            __syncthreads();

            uint32_t ah[4][4], al[4][4];
            int ar0 = wid * 16 + gr;
            #pragma unroll
            for (int ks = 0; ks < 4; ks++) {
                int cp0 = ks * 8 + qc;
                ah[ks][0] = Ah[ar0 * 36 + cp0];
                ah[ks][1] = Ah[(ar0 + 8) * 36 + cp0];
                ah[ks][2] = Ah[ar0 * 36 + cp0 + 4];
                ah[ks][3] = Ah[(ar0 + 8) * 36 + cp0 + 4];
                al[ks][0] = Al[ar0 * 36 + cp0];
                al[ks][1] = Al[(ar0 + 8) * 36 + cp0];
                al[ks][2] = Al[ar0 * 36 + cp0 + 4];
                al[ks][3] = Al[(ar0 + 8) * 36 + cp0 + 4];
            }

            #pragma unroll
            for (int nf = 0; nf < 8; nf++) {
                float d0 = 0.f, d1 = 0.f, d2 = 0.f, d3 = 0.f;
                int bn = nf * 8 + gr;
                #pragma unroll
                for (int ks = 0; ks < 4; ks++) {
                    int kp0 = ks * 8 + qc;
                    uint32_t b0 = Bh[bn * 36 + kp0];
                    uint32_t b1 = Bh[bn * 36 + kp0 + 4];
                    uint32_t c0 = Bl[bn * 36 + kp0];
                    uint32_t c1 = Bl[bn * 36 + kp0 + 4];
                    MMA_BF16(d0, d1, d2, d3, ah[ks][0], ah[ks][1], ah[ks][2], ah[ks][3], b0, b1);
                    MMA_BF16(d0, d1, d2, d3, al[ks][0], al[ks][1], al[ks][2], al[ks][3], b0, b1);
                    MMA_BF16(d0, d1, d2, d3, ah[ks][0], ah[ks][1], ah[ks][2], ah[ks][3], c0, c1);
                }
                int col = tile * 64 + nf * 8 + 2 * qc;
                float bb0 = bp[col], bb1 = bp[col + 1];
                int r1 = row0 + wid * 16 + gr;
                if (r1 < NN) {
                    float2 o = make_float2(fmaxf(d0 + bb0, 0.f), fmaxf(d1 + bb1, 0.f));
                    *(float2*)(out + ((size_t)br * NN + r1) * 640 + col) = o;
                }
                int r2 = r1 + 8;
                if (r2 < NN) {
                    float2 o = make_float2(fmaxf(d2 + bb0, 0.f), fmaxf(d3 + bb1, 0.f));
                    *(float2*)(out + ((size_t)br * NN + r2) * 640 + col) = o;
                }
            }
            __syncthreads();
        }
    }
}

// ---------------- launch ----------------
extern "C" void kernel_launch(void* const* d_in, const int* in_sizes, int n_in,
                              void* d_out, int out_size) {
    const float* x      = (const float*)d_in[0];
    const int4*  edges2 = (const int4*) d_in[1];
    const float* Wb  = (const float*)d_in[2];
    const float* bb  = (const float*)d_in[3];
    const float* Ws1 = (const float*)d_in[4];
    const float* bs1 = (const float*)d_in[5];
    const float* Ws2 = (const float*)d_in[6];
    const float* bs2 = (const float*)d_in[7];
    const float* Ww1 = (const float*)d_in[8];
    const float* bw1 = (const float*)d_in[9];
    const float* Ww2 = (const float*)d_in[10];
    const float* bw2 = (const float*)d_in[11];
    float* out = (float*)d_out;

    __half *hb, *xb, *a2, *xsw1, *a3;
    float *dinv;
    int *cnt;
    uint32_t *WbH, *WbL, *Ws1H, *Ws1L, *Ww1H, *Ww1L;
    cudaGetSymbolAddress((void**)&hb,   g_hb);
    cudaGetSymbolAddress((void**)&xb,   g_xb);
    cudaGetSymbolAddress((void**)&a2,   g_a2);
    cudaGetSymbolAddress((void**)&xsw1, g_xsw1);
    cudaGetSymbolAddress((void**)&a3,   g_a3);
    cudaGetSymbolAddress((void**)&dinv, g_dinv);
    cudaGetSymbolAddress((void**)&cnt,  g_cnt);
    cudaGetSymbolAddress((void**)&WbH,  g_WbH);
    cudaGetSymbolAddress((void**)&WbL,  g_WbL);
    cudaGetSymbolAddress((void**)&Ws1H, g_Ws1H);
    cudaGetSymbolAddress((void**)&Ws1L, g_Ws1L);
    cudaGetSymbolAddress((void**)&Ww1H, g_Ww1H);
    cudaGetSymbolAddress((void**)&Ww1L, g_Ww1L);

    cudaFuncSetAttribute(out_hmma_kernel,
                         cudaFuncAttributeMaxDynamicSharedMemorySize, OH_SMEM);
    cudaFuncSetAttribute(hmma_gemm_kernel<64, 0, 0, 1, 1, 0>,
                         cudaFuncAttributeMaxDynamicSharedMemorySize, 55296);
    cudaFuncSetAttribute(hmma_gemm_kernel<128, 1, 1, 1, 1, 1>,
                         cudaFuncAttributeMaxDynamicSharedMemorySize, 73728);

    const int EB2 = (EE / 2 + 255) / 256;   // 3125
    const int AB = (NN * 32 + 255) / 256;
    const int MB = (NN + 127) / 128;        // 391

    // CSR + degrees + weight prep
    cudaMemsetAsync(cnt, 0, NN * sizeof(int));
    count_prep_kernel<<<EB2 + 256, 256>>>(edges2, Wb, Ws1, Ww1, Ws2, Ww2);
    degscan_kernel<<<NBLK, 1024>>>();
    fill_kernel<<<EB2, 256>>>(edges2);

    // Layer b: hb'(fp16) = dinv .* (x @ Wb)
    hmma_gemm_kernel<64, 0, 0, 1, 1, 0><<<MB, 256, 55296>>>(
        x, 640, 640, WbH, WbL, nullptr, nullptr, nullptr, nullptr, dinv, hb, 64);
    // xb'(fp16) = dinv .* relu(dinv*(sum hb') + bb)
    agg64p_kernel<1, 1, 1><<<AB, 256>>>((const __half2*)hb, xb, bb);
    // a2(fp16) = dinv*(sum xb')
    agg64p_kernel<1, 0, 0><<<AB, 256>>>((const __half2*)xb, a2, nullptr);

    // Fused s1/w1: xsw1'(fp16) = dinv .* relu(a2 @ [Ws1|Ww1] + [bs1|bw1])
    hmma_gemm_kernel<128, 1, 1, 1, 1, 1><<<MB, 256, 73728>>>(
        a2, 64, 64, Ws1H, Ws1L, Ww1H, Ww1L, bs1, bw1, dinv, xsw1, 128);

    // a3(fp16) = dinv*(sum xsw1')
    agg128p_kernel<<<AB, 256>>>((const uint2*)xsw1, a3);

    // s2/w2 via HMMA split-bf16
    out_hmma_kernel<<<MB, 256, OH_SMEM>>>(a3, bs2, bw2, out);
}

// round 15
// speedup vs baseline: 1.0305x; 1.0305x over previous
#include <cuda_runtime.h>
#include <cuda_fp16.h>
#include <math.h>
#include <stdint.h>

#define NN 50000
#define EE 1600000
#define NBLK 49   // ceil(NN/1024)

typedef unsigned long long u64;

// ---------------- scratch ----------------
__device__ int   g_cnt[NN];
__device__ int   g_rowptr[NN + 1];
__device__ int   g_wp[NN];
__device__ int   g_col[EE];
__device__ float g_dinv[NN];
__device__ int   g_bsum[64];
__device__ __half g_hb  [(size_t)NN * 64];    // fp16: dinv .* (x@Wb)
__device__ __half g_xb  [(size_t)NN * 64];    // fp16: dinv .* relu(agg+bb)
__device__ float  g_a2  [(size_t)NN * 64];    // fp32: agg(xb')
__device__ __half g_xsw1[(size_t)NN * 128];   // fp16: dinv .* [xs1|xw1]
__device__ float  g_a3  [(size_t)NN * 128];   // fp32: agg(xsw1')

// precomputed bf16 hi/lo weight splits, layout H[kp * N + n] = pack(W[2kp][n], W[2kp+1][n])
__device__ uint32_t g_WbH [320 * 64], g_WbL [320 * 64];
__device__ uint32_t g_Ws1H[32 * 64],  g_Ws1L[32 * 64];
__device__ uint32_t g_Ww1H[32 * 64],  g_Ww1L[32 * 64];
__device__ uint32_t g_Ws2H[32 * 640], g_Ws2L[32 * 640];
__device__ uint32_t g_Ww2H[32 * 640], g_Ww2L[32 * 640];

// ---------------- bf16 split helpers ----------------
__device__ __forceinline__ uint32_t cvt_bf2(float a, float b) {
    uint32_t r;
    asm("cvt.rn.satfinite.bf16x2.f32 %0, %1, %2;" : "=r"(r) : "f"(b), "f"(a));
    return r;
}
__device__ __forceinline__ float bf_lo_f(uint32_t h) { return __uint_as_float((h & 0xFFFFu) << 16); }
__device__ __forceinline__ float bf_hi_f(uint32_t h) { return __uint_as_float(h & 0xFFFF0000u); }

#define MMA_BF16(d0, d1, d2, d3, a0, a1, a2, a3, b0, b1) \
    asm volatile("mma.sync.aligned.m16n8k16.row.col.f32.bf16.bf16.f32 " \
        "{%0,%1,%2,%3}, {%4,%5,%6,%7}, {%8,%9}, {%0,%1,%2,%3};" \
        : "+f"(d0), "+f"(d1), "+f"(d2), "+f"(d3) \
        : "r"(a0), "r"(a1), "r"(a2), "r"(a3), "r"(b0), "r"(b1))

// ---------------- weight prep: fp32 -> bf16 hi/lo packed pairs ----------------
__device__ __forceinline__ void conv_pair(const float* __restrict__ W, int N, int i,
                                          uint32_t* __restrict__ H, uint32_t* __restrict__ L) {
    int kp = i / N, n = i - kp * N;
    float f0 = W[(size_t)(2 * kp)     * N + n];
    float f1 = W[(size_t)(2 * kp + 1) * N + n];
    uint32_t h = cvt_bf2(f0, f1);
    float r0 = f0 - bf_lo_f(h), r1 = f1 - bf_hi_f(h);
    H[i] = h;
    L[i] = cvt_bf2(r0, r1);
}

__global__ void prep_weights_kernel(const float* __restrict__ Wb,
                                    const float* __restrict__ Ws1,
                                    const float* __restrict__ Ww1,
                                    const float* __restrict__ Ws2,
                                    const float* __restrict__ Ww2) {
    int idx = blockIdx.x * blockDim.x + threadIdx.x;
    if (idx < 20480)                      conv_pair(Wb,  64,  idx,          g_WbH,  g_WbL);
    else if (idx < 22528)                 conv_pair(Ws1, 64,  idx - 20480,  g_Ws1H, g_Ws1L);
    else if (idx < 24576)                 conv_pair(Ww1, 64,  idx - 22528,  g_Ww1H, g_Ww1L);
    else if (idx < 45056)                 conv_pair(Ws2, 640, idx - 24576,  g_Ws2H, g_Ws2L);
    else if (idx < 65536)                 conv_pair(Ww2, 640, idx - 45056,  g_Ww2H, g_Ww2L);
}

// ---------------- CSR build (R13) ----------------
__global__ void count_kernel(const int4* __restrict__ edges2) {
    int e = blockIdx.x * blockDim.x + threadIdx.x;
    if (e < EE / 2) {
        int4 ed = edges2[e];
        atomicAdd(&g_cnt[ed.y], 1);
        atomicAdd(&g_cnt[ed.w], 1);
    }
}
__global__ void degsum_kernel() {
    __shared__ int ws[32];
    int tid = threadIdx.x;
    int i = blockIdx.x * 1024 + tid;
    int v = (i < NN) ? g_cnt[i] : 0;
    if (i < NN) g_dinv[i] = rsqrtf((float)v + 1.0f);
    int x = v;
    #pragma unroll
    for (int off = 16; off; off >>= 1) x += __shfl_down_sync(0xffffffffu, x, off);
    if ((tid & 31) == 0) ws[tid >> 5] = x;
    __syncthreads();
    if (tid < 32) {
        int y = ws[tid];
        #pragma unroll
        for (int off = 16; off; off >>= 1) y += __shfl_down_sync(0xffffffffu, y, off);
        if (tid == 0) g_bsum[blockIdx.x] = y;
    }
}
__global__ void scanapply_kernel() {
    __shared__ int warpsums[32];
    __shared__ int sb[64];
    int tid = threadIdx.x, lane = tid & 31, wid = tid >> 5;
    if (tid < 64) sb[tid] = (tid < NBLK) ? g_bsum[tid] : 0;
    __syncthreads();
    #pragma unroll
    for (int off = 1; off < 64; off <<= 1) {
        int t = 0;
        if (tid < 64 && tid >= off) t = sb[tid - off];
        __syncthreads();
        if (tid < 64) sb[tid] += t;
        __syncthreads();
    }
    if (blockIdx.x == 0 && tid == 0) g_rowptr[NN] = sb[NBLK - 1];
    int boff = (blockIdx.x > 0) ? sb[blockIdx.x - 1] : 0;

    int i = blockIdx.x * 1024 + tid;
    int v = (i < NN) ? g_cnt[i] : 0;
    int x = v;
    #pragma unroll
    for (int off = 1; off < 32; off <<= 1) {
        int y = __shfl_up_sync(0xffffffffu, x, off);
        if (lane >= off) x += y;
    }
    if (lane == 31) warpsums[wid] = x;
    __syncthreads();
    if (wid == 0) {
        int w = warpsums[lane];
        #pragma unroll
        for (int off = 1; off < 32; off <<= 1) {
            int y = __shfl_up_sync(0xffffffffu, w, off);
            if (lane >= off) w += y;
        }
        warpsums[lane] = w;
    }
    __syncthreads();
    int excl = boff + ((wid > 0) ? warpsums[wid - 1] : 0) + x - v;
    if (i < NN) {
        g_rowptr[i] = excl;
        g_wp[i]     = excl;
    }
}
__global__ void fill_kernel(const int4* __restrict__ edges2) {
    int e = blockIdx.x * blockDim.x + threadIdx.x;
    if (e < EE / 2) {
        int4 ed = edges2[e];
        int p0 = atomicAdd(&g_wp[ed.y], 1);
        g_col[p0] = ed.x;
        int p1 = atomicAdd(&g_wp[ed.w], 1);
        g_col[p1] = ed.z;
    }
}

// ---------------- aggregation (R13, unchanged) ----------------
template<int OUTH, int PRE, int RELU>
__global__ void agg64p_kernel(const __half2* __restrict__ X, void* __restrict__ out,
                              const float* __restrict__ bias) {
    int idx  = blockIdx.x * blockDim.x + threadIdx.x;
    int node = idx >> 5;
    if (node >= NN) return;
    int lane = idx & 31;
    float2 v = __half22float2(X[node * 32 + lane]);
    float ax = v.x, ay = v.y;
    float bx = 0.f, by = 0.f;
    int e = g_rowptr[node], end = g_rowptr[node + 1];
    while (e < end) {
        int n = end - e;
        if (n > 32) n = 32;
        int c = (lane < n) ? __ldg(&g_col[e + lane]) : 0;
        int j = 0;
        for (; j + 4 <= n; j += 4) {
            int s0 = __shfl_sync(0xffffffffu, c, j);
            int s1 = __shfl_sync(0xffffffffu, c, j + 1);
            int s2 = __shfl_sync(0xffffffffu, c, j + 2);
            int s3 = __shfl_sync(0xffffffffu, c, j + 3);
            float2 u0 = __half22float2(X[s0 * 32 + lane]);
            float2 u1 = __half22float2(X[s1 * 32 + lane]);
            float2 u2 = __half22float2(X[s2 * 32 + lane]);
            float2 u3 = __half22float2(X[s3 * 32 + lane]);
            ax += u0.x + u1.x; ay += u0.y + u1.y;
            bx += u2.x + u3.x; by += u2.y + u3.y;
        }
        for (; j < n; j++) {
            int s = __shfl_sync(0xffffffffu, c, j);
            float2 u = __half22float2(X[s * 32 + lane]);
            ax += u.x; ay += u.y;
        }
        e += n;
    }
    ax += bx; ay += by;
    float dv = g_dinv[node];
    ax *= dv; ay *= dv;
    if (bias) { ax += bias[lane * 2]; ay += bias[lane * 2 + 1]; }
    if (RELU) { ax = fmaxf(ax, 0.f); ay = fmaxf(ay, 0.f); }
    if (PRE) { ax *= dv; ay *= dv; }
    if (OUTH) ((__half2*)out)[node * 32 + lane] = __floats2half2_rn(ax, ay);
    else      ((float2*)out)[node * 32 + lane]  = make_float2(ax, ay);
}

__global__ void agg128p_kernel(const uint2* __restrict__ X, float* __restrict__ out) {
    int idx  = blockIdx.x * blockDim.x + threadIdx.x;
    int node = idx >> 5;
    if (node >= NN) return;
    int lane = idx & 31;
    uint2 raw = X[node * 32 + lane];
    float2 p0 = __half22float2(*(const __half2*)&raw.x);
    float2 p1 = __half22float2(*(const __half2*)&raw.y);
    float a0 = p0.x, a1 = p0.y, a2 = p1.x, a3 = p1.y;
    float b0 = 0.f, b1 = 0.f, b2 = 0.f, b3 = 0.f;
    int e = g_rowptr[node], end = g_rowptr[node + 1];
    while (e < end) {
        int n = end - e;
        if (n > 32) n = 32;
        int c = (lane < n) ? __ldg(&g_col[e + lane]) : 0;
        int j = 0;
        for (; j + 4 <= n; j += 4) {
            int s0 = __shfl_sync(0xffffffffu, c, j);
            int s1 = __shfl_sync(0xffffffffu, c, j + 1);
            int s2 = __shfl_sync(0xffffffffu, c, j + 2);
            int s3 = __shfl_sync(0xffffffffu, c, j + 3);
            uint2 r0 = X[s0 * 32 + lane];
            uint2 r1 = X[s1 * 32 + lane];
            uint2 r2 = X[s2 * 32 + lane];
            uint2 r3 = X[s3 * 32 + lane];
            float2 q;
            q = __half22float2(*(const __half2*)&r0.x); a0 += q.x; a1 += q.y;
            q = __half22float2(*(const __half2*)&r0.y); a2 += q.x; a3 += q.y;
            q = __half22float2(*(const __half2*)&r1.x); b0 += q.x; b1 += q.y;
            q = __half22float2(*(const __half2*)&r1.y); b2 += q.x; b3 += q.y;
            q = __half22float2(*(const __half2*)&r2.x); a0 += q.x; a1 += q.y;
            q = __half22float2(*(const __half2*)&r2.y); a2 += q.x; a3 += q.y;
            q = __half22float2(*(const __half2*)&r3.x); b0 += q.x; b1 += q.y;
            q = __half22float2(*(const __half2*)&r3.y); b2 += q.x; b3 += q.y;
        }
        for (; j < n; j++) {
            int s = __shfl_sync(0xffffffffu, c, j);
            uint2 r = X[s * 32 + lane];
            float2 q;
            q = __half22float2(*(const __half2*)&r.x); a0 += q.x; a1 += q.y;
            q = __half22float2(*(const __half2*)&r.y); a2 += q.x; a3 += q.y;
        }
        e += n;
    }
    a0 += b0; a1 += b1; a2 += b2; a3 += b3;
    float dv = g_dinv[node];
    a0 *= dv; a1 *= dv; a2 *= dv; a3 *= dv;
    ((float4*)out)[node * 32 + lane] = make_float4(a0, a1, a2, a3);
}

// ---------------- unified HMMA split-bf16 GEMM (ks-outer loop, low regs) ----------------
// B source: BH0/BL0 (+ BH1/BL1 if NT=128), layout [kp * 64 + n], kp global k-pair.
template<int NT, int RELU, int BIAS, int OUTH, int RS, int MINB>
__global__ void __launch_bounds__(256, MINB)
hmma_gemm_kernel(const float* __restrict__ A, int lda, int K,
                 const uint32_t* __restrict__ BH0, const uint32_t* __restrict__ BL0,
                 const uint32_t* __restrict__ BH1, const uint32_t* __restrict__ BL1,
                 const float* __restrict__ bias0, const float* __restrict__ bias1,
                 const float* __restrict__ rowscale,
                 void* __restrict__ C, int ldc) {
    extern __shared__ char smem[];
    uint32_t* Ah = (uint32_t*)smem;
    uint32_t* Al = (uint32_t*)(smem + 18432);
    uint32_t* Bh = (uint32_t*)(smem + 36864);
    uint32_t* Bl = (uint32_t*)(smem + 36864 + NT * 144);

    int tid  = threadIdx.x;
    int wid  = tid >> 5, lane = tid & 31;
    int gr   = lane >> 2;
    int qc   = lane & 3;
    int row0 = blockIdx.x * 128;
    constexpr int NF = NT / 8;

    float d[NF][4];
    #pragma unroll
    for (int nf = 0; nf < NF; nf++) {
        d[nf][0] = 0.f; d[nf][1] = 0.f; d[nf][2] = 0.f; d[nf][3] = 0.f;
    }

    for (int k0 = 0; k0 < K; k0 += 64) {
        #pragma unroll
        for (int j = 0; j < 16; j++) {
            int idx = tid + j * 256;
            int r = idx >> 5, cp = idx & 31;
            float2 v = make_float2(0.f, 0.f);
            int grow = row0 + r;
            if (grow < NN) v = *(const float2*)(A + (size_t)grow * lda + k0 + 2 * cp);
            uint32_t h = cvt_bf2(v.x, v.y);
            float rx = v.x - bf_lo_f(h), ry = v.y - bf_hi_f(h);
            Ah[r * 36 + cp] = h;
            Al[r * 36 + cp] = cvt_bf2(rx, ry);
        }
        #pragma unroll
        for (int j = 0; j < NT / 8; j++) {
            int idx = tid + j * 256;
            int n  = idx % NT;
            int kp = idx / NT;
            int gkp = (k0 >> 1) + kp;
            const uint32_t* H = BH0;
            const uint32_t* L = BL0;
            int cc = n;
            if (NT == 128 && n >= 64) { H = BH1; L = BL1; cc = n - 64; }
            Bh[n * 36 + kp] = H[gkp * 64 + cc];
            Bl[n * 36 + kp] = L[gkp * 64 + cc];
        }
        __syncthreads();

        int ar0 = wid * 16 + gr;
        #pragma unroll
        for (int ks = 0; ks < 4; ks++) {
            int cp0 = ks * 8 + qc;
            uint32_t a0 = Ah[ar0 * 36 + cp0];
            uint32_t a1 = Ah[(ar0 + 8) * 36 + cp0];
            uint32_t a2 = Ah[ar0 * 36 + cp0 + 4];
            uint32_t a3 = Ah[(ar0 + 8) * 36 + cp0 + 4];
            uint32_t l0 = Al[ar0 * 36 + cp0];
            uint32_t l1 = Al[(ar0 + 8) * 36 + cp0];
            uint32_t l2 = Al[ar0 * 36 + cp0 + 4];
            uint32_t l3 = Al[(ar0 + 8) * 36 + cp0 + 4];
            #pragma unroll
            for (int nf = 0; nf < NF; nf++) {
                int bn = nf * 8 + gr;
                uint32_t b0 = Bh[bn * 36 + cp0];
                uint32_t b1 = Bh[bn * 36 + cp0 + 4];
                uint32_t c0 = Bl[bn * 36 + cp0];
                uint32_t c1 = Bl[bn * 36 + cp0 + 4];
                MMA_BF16(d[nf][0], d[nf][1], d[nf][2], d[nf][3], a0, a1, a2, a3, b0, b1);
                MMA_BF16(d[nf][0], d[nf][1], d[nf][2], d[nf][3], l0, l1, l2, l3, b0, b1);
                MMA_BF16(d[nf][0], d[nf][1], d[nf][2], d[nf][3], a0, a1, a2, a3, c0, c1);
            }
        }
        __syncthreads();
    }

    int r1 = row0 + wid * 16 + gr;
    int r2 = r1 + 8;
    float rs1 = 1.f, rs2 = 1.f;
    if (RS) {
        if (r1 < NN) rs1 = rowscale[r1];
        if (r2 < NN) rs2 = rowscale[r2];
    }
    #pragma unroll
    for (int nf = 0; nf < NF; nf++) {
        int col = nf * 8 + 2 * qc;
        float bb0 = 0.f, bb1 = 0.f;
        if (BIAS) {
            const float* bp = bias0;
            int cc = col;
            if (NT == 128 && col >= 64 && bias1) { bp = bias1; cc = col - 64; }
            bb0 = bp[cc]; bb1 = bp[cc + 1];
        }
        float o0 = d[nf][0] + bb0, o1 = d[nf][1] + bb1;
        float o2 = d[nf][2] + bb0, o3 = d[nf][3] + bb1;
        if (RELU) {
            o0 = fmaxf(o0, 0.f); o1 = fmaxf(o1, 0.f);
            o2 = fmaxf(o2, 0.f); o3 = fmaxf(o3, 0.f);
        }
        if (RS) { o0 *= rs1; o1 *= rs1; o2 *= rs2; o3 *= rs2; }
        if (OUTH) {
            if (r1 < NN) *(__half2*)((__half*)C + (size_t)r1 * ldc + col) = __floats2half2_rn(o0, o1);
            if (r2 < NN) *(__half2*)((__half*)C + (size_t)r2 * ldc + col) = __floats2half2_rn(o2, o3);
        } else {
            if (r1 < NN) *(float2*)((float*)C + (size_t)r1 * ldc + col) = make_float2(o0, o1);
            if (r2 < NN) *(float2*)((float*)C + (size_t)r2 * ldc + col) = make_float2(o2, o3);
        }
    }
}

// ---------------- s2/w2: HMMA split-bf16, precomputed W splits (R13) ----------------
#define OH_SMEM 60416

__global__ void __launch_bounds__(256)
out_hmma_kernel(const float* __restrict__ a3,
                const float* __restrict__ bs2, const float* __restrict__ bw2,
                float* __restrict__ out) {
    extern __shared__ char smem[];
    float*    sbias = (float*)smem;
    uint32_t* Ah = (uint32_t*)(smem + 5120);
    uint32_t* Al = (uint32_t*)(smem + 23552);
    uint32_t* Bh = (uint32_t*)(smem + 41984);
    uint32_t* Bl = (uint32_t*)(smem + 51200);

    int tid  = threadIdx.x;
    int wid  = tid >> 5, lane = tid & 31;
    int gr   = lane >> 2;
    int qc   = lane & 3;
    int row0 = blockIdx.x * 128;

    for (int i = tid; i < 640; i += 256) { sbias[i] = bs2[i]; sbias[640 + i] = bw2[i]; }

    #pragma unroll 1
    for (int br = 0; br < 2; br++) {
        __syncthreads();
        for (int idx = tid; idx < 128 * 32; idx += 256) {
            int r  = idx >> 5;
            int cp = idx & 31;
            float2 v = make_float2(0.f, 0.f);
            int grow = row0 + r;
            if (grow < NN) v = *(const float2*)(a3 + (size_t)grow * 128 + br * 64 + 2 * cp);
            uint32_t h = cvt_bf2(v.x, v.y);
            float rx = v.x - bf_lo_f(h), ry = v.y - bf_hi_f(h);
            Ah[r * 36 + cp] = h;
            Al[r * 36 + cp] = cvt_bf2(rx, ry);
        }
        __syncthreads();
        const uint32_t* WH = br ? g_Ww2H : g_Ws2H;
        const uint32_t* WL = br ? g_Ww2L : g_Ws2L;
        const float* bp = sbias + br * 640;

        #pragma unroll 1
        for (int tile = 0; tile < 10; tile++) {
            for (int idx = tid; idx < 64 * 32; idx += 256) {
                int n  = idx & 63;
                int kp = idx >> 6;
                Bh[n * 36 + kp] = WH[kp * 640 + tile * 64 + n];
                Bl[n * 36 + kp] = WL[kp * 640 + tile * 64 + n];
            }
            __syncthreads();

            int ar0 = wid * 16 + gr;
            #pragma unroll
            for (int nf = 0; nf < 8; nf++) {
                float d0 = 0.f, d1 = 0.f, d2 = 0.f, d3 = 0.f;
                int bn = nf * 8 + gr;
                #pragma unroll
                for (int ks = 0; ks < 4; ks++) {
                    int cp0 = ks * 8 + qc;
                    uint32_t a0 = Ah[ar0 * 36 + cp0];
                    uint32_t a1 = Ah[(ar0 + 8) * 36 + cp0];
                    uint32_t a2 = Ah[ar0 * 36 + cp0 + 4];
                    uint32_t a3v = Ah[(ar0 + 8) * 36 + cp0 + 4];
                    uint32_t l0 = Al[ar0 * 36 + cp0];
                    uint32_t l1 = Al[(ar0 + 8) * 36 + cp0];
                    uint32_t l2 = Al[ar0 * 36 + cp0 + 4];
                    uint32_t l3 = Al[(ar0 + 8) * 36 + cp0 + 4];
                    uint32_t b0 = Bh[bn * 36 + cp0];
                    uint32_t b1 = Bh[bn * 36 + cp0 + 4];
                    uint32_t c0 = Bl[bn * 36 + cp0];
                    uint32_t c1 = Bl[bn * 36 + cp0 + 4];
                    MMA_BF16(d0, d1, d2, d3, a0, a1, a2, a3v, b0, b1);
                    MMA_BF16(d0, d1, d2, d3, l0, l1, l2, l3, b0, b1);
                    MMA_BF16(d0, d1, d2, d3, a0, a1, a2, a3v, c0, c1);
                }
                int col = tile * 64 + nf * 8 + 2 * qc;
                float bb0 = bp[col], bb1 = bp[col + 1];
                int r1 = row0 + wid * 16 + gr;
                if (r1 < NN) {
                    float2 o = make_float2(fmaxf(d0 + bb0, 0.f), fmaxf(d1 + bb1, 0.f));
                    *(float2*)(out + ((size_t)br * NN + r1) * 640 + col) = o;
                }
                int r2 = r1 + 8;
                if (r2 < NN) {
                    float2 o = make_float2(fmaxf(d2 + bb0, 0.f), fmaxf(d3 + bb1, 0.f));
                    *(float2*)(out + ((size_t)br * NN + r2) * 640 + col) = o;
                }
            }
            __syncthreads();
        }
    }
}

// ---------------- launch ----------------
extern "C" void kernel_launch(void* const* d_in, const int* in_sizes, int n_in,
                              void* d_out, int out_size) {
    const float* x      = (const float*)d_in[0];
    const int4*  edges2 = (const int4*) d_in[1];
    const float* Wb  = (const float*)d_in[2];
    const float* bb  = (const float*)d_in[3];
    const float* Ws1 = (const float*)d_in[4];
    const float* bs1 = (const float*)d_in[5];
    const float* Ws2 = (const float*)d_in[6];
    const float* bs2 = (const float*)d_in[7];
    const float* Ww1 = (const float*)d_in[8];
    const float* bw1 = (const float*)d_in[9];
    const float* Ww2 = (const float*)d_in[10];
    const float* bw2 = (const float*)d_in[11];
    float* out = (float*)d_out;

    __half *hb, *xb, *xsw1;
    float  *a2, *a3, *dinv;
    int *cnt;
    uint32_t *WbH, *WbL, *Ws1H, *Ws1L, *Ww1H, *Ww1L;
    cudaGetSymbolAddress((void**)&hb,   g_hb);
    cudaGetSymbolAddress((void**)&xb,   g_xb);
    cudaGetSymbolAddress((void**)&a2,   g_a2);
    cudaGetSymbolAddress((void**)&xsw1, g_xsw1);
    cudaGetSymbolAddress((void**)&a3,   g_a3);
    cudaGetSymbolAddress((void**)&dinv, g_dinv);
    cudaGetSymbolAddress((void**)&cnt,  g_cnt);
    cudaGetSymbolAddress((void**)&WbH,  g_WbH);
    cudaGetSymbolAddress((void**)&WbL,  g_WbL);
    cudaGetSymbolAddress((void**)&Ws1H, g_Ws1H);
    cudaGetSymbolAddress((void**)&Ws1L, g_Ws1L);
    cudaGetSymbolAddress((void**)&Ww1H, g_Ww1H);
    cudaGetSymbolAddress((void**)&Ww1L, g_Ww1L);

    cudaFuncSetAttribute(out_hmma_kernel,
                         cudaFuncAttributeMaxDynamicSharedMemorySize, OH_SMEM);
    cudaFuncSetAttribute(hmma_gemm_kernel<64, 0, 0, 1, 1, 3>,
                         cudaFuncAttributeMaxDynamicSharedMemorySize, 55296);
    cudaFuncSetAttribute(hmma_gemm_kernel<128, 1, 1, 1, 1, 1>,
                         cudaFuncAttributeMaxDynamicSharedMemorySize, 73728);

    const int EB2 = (EE / 2 + 255) / 256;
    const int AB = (NN * 32 + 255) / 256;
    const int MB = (NN + 127) / 128;   // 391

    // Weight splits
    prep_weights_kernel<<<256, 256>>>(Wb, Ws1, Ww1, Ws2, Ww2);

    // CSR + degrees
    cudaMemsetAsync(cnt, 0, NN * sizeof(int));
    count_kernel<<<EB2, 256>>>(edges2);
    degsum_kernel<<<NBLK, 1024>>>();
    scanapply_kernel<<<NBLK, 1024>>>();
    fill_kernel<<<EB2, 256>>>(edges2);

    // Layer b: hb'(fp16) = dinv .* (x @ Wb)   [3 blocks/SM -> single wave]
    hmma_gemm_kernel<64, 0, 0, 1, 1, 3><<<MB, 256, 55296>>>(
        x, 640, 640, WbH, WbL, nullptr, nullptr, nullptr, nullptr, dinv, hb, 64);
    // xb'(fp16) = dinv .* relu(dinv*(sum hb') + bb)
    agg64p_kernel<1, 1, 1><<<AB, 256>>>((const __half2*)hb, xb, bb);
    // a2(fp32) = dinv*(sum xb')
    agg64p_kernel<0, 0, 0><<<AB, 256>>>((const __half2*)xb, a2, nullptr);

    // Fused s1/w1: xsw1'(fp16) = dinv .* relu(a2 @ [Ws1|Ww1] + [bs1|bw1])
    hmma_gemm_kernel<128, 1, 1, 1, 1, 1><<<MB, 256, 73728>>>(
        a2, 64, 64, Ws1H, Ws1L, Ww1H, Ww1L, bs1, bw1, dinv, xsw1, 128);

    // a3(fp32) = dinv*(sum xsw1')
    agg128p_kernel<<<AB, 256>>>((const uint2*)xsw1, a3);

    // s2/w2 via HMMA split-bf16
    out_hmma_kernel<<<MB, 256, OH_SMEM>>>(a3, bs2, bw2, out);
}